// round 1
// baseline (speedup 1.0000x reference)
#include <cuda_runtime.h>

#define BB 8
#define CC 256
#define NN 2048

// Scratch (allocation-free: device globals)
__device__ float g_Qt[BB * NN * CC];            // [b][n][c]  (Q transposed)
__device__ float g_Kt[BB * NN * CC];            // [b][m][c]  (K transposed)
__device__ float g_V [BB * CC * NN];            // [b][c][m]
__device__ float g_S [(size_t)BB * NN * NN];    // [b][n][m]  scores / probs

// ---------------------------------------------------------------------------
// Kernel 1: QKV projection.  Q[b,o,n] = sum_c Wq[o,c] x[b,c,n] + bq[o], etc.
// Block tile: 64 (o) x 64 (n), BK=16.  256 threads, 4x4 per thread, 3 outputs.
// Writes Qt/Kt transposed [b][n][c], V as [b][c][n].
// ---------------------------------------------------------------------------
__global__ __launch_bounds__(256) void qkv_kernel(
    const float* __restrict__ x,
    const float* __restrict__ Wq, const float* __restrict__ bq,
    const float* __restrict__ Wk, const float* __restrict__ bk,
    const float* __restrict__ Wv, const float* __restrict__ bv)
{
    __shared__ __align__(16) float xs [16][68];
    __shared__ __align__(16) float wqs[16][68];
    __shared__ __align__(16) float wks[16][68];
    __shared__ __align__(16) float wvs[16][68];

    const int n0 = blockIdx.x * 64;
    const int o0 = blockIdx.y * 64;
    const int b  = blockIdx.z;
    const int tid = threadIdx.x;
    const int tx = tid & 15;   // n direction
    const int ty = tid >> 4;   // o direction

    float aq[4][4] = {}, ak[4][4] = {}, av[4][4] = {};

    const float* xb = x + (size_t)b * CC * NN;

    for (int k0 = 0; k0 < CC; k0 += 16) {
        // x tile: 16 (k) x 64 (n)
        {
            const int kk = tid >> 4, j4 = tid & 15;
            float4 v = *(const float4*)&xb[(size_t)(k0 + kk) * NN + n0 + j4 * 4];
            *(float4*)&xs[kk][j4 * 4] = v;
        }
        // weight tiles: 64 (o) x 16 (k), stored transposed [k][o]
        {
            const int r = tid >> 2, k4 = tid & 3;
            const int wo = (o0 + r) * CC + k0 + k4 * 4;
            float4 q4 = *(const float4*)&Wq[wo];
            float4 k4v = *(const float4*)&Wk[wo];
            float4 v4 = *(const float4*)&Wv[wo];
            wqs[k4*4+0][r] = q4.x; wqs[k4*4+1][r] = q4.y; wqs[k4*4+2][r] = q4.z; wqs[k4*4+3][r] = q4.w;
            wks[k4*4+0][r] = k4v.x; wks[k4*4+1][r] = k4v.y; wks[k4*4+2][r] = k4v.z; wks[k4*4+3][r] = k4v.w;
            wvs[k4*4+0][r] = v4.x; wvs[k4*4+1][r] = v4.y; wvs[k4*4+2][r] = v4.z; wvs[k4*4+3][r] = v4.w;
        }
        __syncthreads();

        #pragma unroll
        for (int kk = 0; kk < 16; kk++) {
            float4 xf = *(const float4*)&xs [kk][tx * 4];
            float4 qf = *(const float4*)&wqs[kk][ty * 4];
            float4 kf = *(const float4*)&wks[kk][ty * 4];
            float4 vf = *(const float4*)&wvs[kk][ty * 4];
            float xr[4] = {xf.x, xf.y, xf.z, xf.w};
            float qr[4] = {qf.x, qf.y, qf.z, qf.w};
            float kr[4] = {kf.x, kf.y, kf.z, kf.w};
            float vr[4] = {vf.x, vf.y, vf.z, vf.w};
            #pragma unroll
            for (int i = 0; i < 4; i++)
                #pragma unroll
                for (int j = 0; j < 4; j++) {
                    aq[i][j] += qr[i] * xr[j];
                    ak[i][j] += kr[i] * xr[j];
                    av[i][j] += vr[i] * xr[j];
                }
        }
        __syncthreads();
    }

    float bqv[4], bkv[4], bvv[4];
    #pragma unroll
    for (int i = 0; i < 4; i++) {
        bqv[i] = bq[o0 + ty * 4 + i];
        bkv[i] = bk[o0 + ty * 4 + i];
        bvv[i] = bv[o0 + ty * 4 + i];
    }

    // Qt/Kt: [b][n][c] -> float4 contiguous over o (i index)
    #pragma unroll
    for (int j = 0; j < 4; j++) {
        const int n = n0 + tx * 4 + j;
        const size_t base = ((size_t)b * NN + n) * CC + o0 + ty * 4;
        float4 q4 = make_float4(aq[0][j] + bqv[0], aq[1][j] + bqv[1],
                                aq[2][j] + bqv[2], aq[3][j] + bqv[3]);
        float4 k4 = make_float4(ak[0][j] + bkv[0], ak[1][j] + bkv[1],
                                ak[2][j] + bkv[2], ak[3][j] + bkv[3]);
        *(float4*)&g_Qt[base] = q4;
        *(float4*)&g_Kt[base] = k4;
    }
    // V: [b][c][n] -> float4 contiguous over n (j index)
    #pragma unroll
    for (int i = 0; i < 4; i++) {
        const int o = o0 + ty * 4 + i;
        const size_t base = ((size_t)b * CC + o) * NN + n0 + tx * 4;
        float4 v4 = make_float4(av[i][0] + bvv[i], av[i][1] + bvv[i],
                                av[i][2] + bvv[i], av[i][3] + bvv[i]);
        *(float4*)&g_V[base] = v4;
    }
}

// ---------------------------------------------------------------------------
// Kernel 2: scores  S[b,n,m] = scale * sum_c Qt[b,n,c] * Kt[b,m,c]
// NT SGEMM 2048x2048x256 per batch. 64x64 tile, BK=16, 4x4 per thread.
// ---------------------------------------------------------------------------
__global__ __launch_bounds__(256) void scores_kernel()
{
    __shared__ __align__(16) float As[16][68];
    __shared__ __align__(16) float Bs[16][68];

    const int m0 = blockIdx.x * 64;
    const int n0 = blockIdx.y * 64;
    const int b  = blockIdx.z;
    const int tid = threadIdx.x;
    const int tx = tid & 15;   // m direction
    const int ty = tid >> 4;   // n direction

    float acc[4][4] = {};

    const float* Qb = g_Qt + (size_t)b * NN * CC;
    const float* Kb = g_Kt + (size_t)b * NN * CC;

    const int r  = tid >> 2;
    const int k4 = tid & 3;

    for (int k0 = 0; k0 < CC; k0 += 16) {
        float4 a4 = *(const float4*)&Qb[(size_t)(n0 + r) * CC + k0 + k4 * 4];
        float4 b4 = *(const float4*)&Kb[(size_t)(m0 + r) * CC + k0 + k4 * 4];
        As[k4*4+0][r] = a4.x; As[k4*4+1][r] = a4.y; As[k4*4+2][r] = a4.z; As[k4*4+3][r] = a4.w;
        Bs[k4*4+0][r] = b4.x; Bs[k4*4+1][r] = b4.y; Bs[k4*4+2][r] = b4.z; Bs[k4*4+3][r] = b4.w;
        __syncthreads();

        #pragma unroll
        for (int kk = 0; kk < 16; kk++) {
            float4 af = *(const float4*)&As[kk][ty * 4];
            float4 bf = *(const float4*)&Bs[kk][tx * 4];
            float ar[4] = {af.x, af.y, af.z, af.w};
            float br[4] = {bf.x, bf.y, bf.z, bf.w};
            #pragma unroll
            for (int i = 0; i < 4; i++)
                #pragma unroll
                for (int j = 0; j < 4; j++)
                    acc[i][j] += ar[i] * br[j];
        }
        __syncthreads();
    }

    const float scale = 1.0f / 16.0f;  // 1/sqrt(256)
    #pragma unroll
    for (int i = 0; i < 4; i++) {
        const int n = n0 + ty * 4 + i;
        float4 s4 = make_float4(acc[i][0] * scale, acc[i][1] * scale,
                                acc[i][2] * scale, acc[i][3] * scale);
        *(float4*)&g_S[(size_t)b * NN * NN + (size_t)n * NN + m0 + tx * 4] = s4;
    }
}

// ---------------------------------------------------------------------------
// Kernel 3: row softmax over m (2048 elems), in place on g_S.
// One block of 256 threads per row; 8 elems/thread, register resident.
// ---------------------------------------------------------------------------
__global__ __launch_bounds__(256) void softmax_kernel()
{
    __shared__ float redmax[8];
    __shared__ float redsum[8];

    const size_t row = blockIdx.x;            // b*NN + n
    float* p = g_S + row * NN;
    const int tid  = threadIdx.x;
    const int lane = tid & 31;
    const int warp = tid >> 5;

    float v[8];
    float mx = -3.4e38f;
    #pragma unroll
    for (int t = 0; t < 8; t++) {
        v[t] = p[tid + t * 256];
        mx = fmaxf(mx, v[t]);
    }
    #pragma unroll
    for (int o = 16; o > 0; o >>= 1)
        mx = fmaxf(mx, __shfl_xor_sync(0xffffffffu, mx, o));
    if (lane == 0) redmax[warp] = mx;
    __syncthreads();
    if (warp == 0) {
        float w = (lane < 8) ? redmax[lane] : -3.4e38f;
        #pragma unroll
        for (int o = 4; o > 0; o >>= 1)
            w = fmaxf(w, __shfl_xor_sync(0xffffffffu, w, o));
        if (lane == 0) redmax[0] = w;
    }
    __syncthreads();
    mx = redmax[0];

    float s = 0.0f;
    #pragma unroll
    for (int t = 0; t < 8; t++) {
        v[t] = __expf(v[t] - mx);
        s += v[t];
    }
    #pragma unroll
    for (int o = 16; o > 0; o >>= 1)
        s += __shfl_xor_sync(0xffffffffu, s, o);
    if (lane == 0) redsum[warp] = s;
    __syncthreads();
    if (warp == 0) {
        float w = (lane < 8) ? redsum[lane] : 0.0f;
        #pragma unroll
        for (int o = 4; o > 0; o >>= 1)
            w += __shfl_xor_sync(0xffffffffu, w, o);
        if (lane == 0) redsum[0] = w;
    }
    __syncthreads();
    const float inv = 1.0f / redsum[0];

    #pragma unroll
    for (int t = 0; t < 8; t++)
        p[tid + t * 256] = v[t] * inv;
}

// ---------------------------------------------------------------------------
// Kernel 4: out[b,c,n] = sum_m P[b,n,m] * V[b,c,m] + x[b,c,n]
// NT SGEMM 256x2048x2048 per batch, fused residual.
// ---------------------------------------------------------------------------
__global__ __launch_bounds__(256) void out_kernel(
    const float* __restrict__ x, float* __restrict__ out)
{
    __shared__ __align__(16) float As[16][68];   // V tile [k=m][c]
    __shared__ __align__(16) float Bs[16][68];   // P tile [k=m][n]

    const int n0 = blockIdx.x * 64;
    const int c0 = blockIdx.y * 64;
    const int b  = blockIdx.z;
    const int tid = threadIdx.x;
    const int tx = tid & 15;   // n direction
    const int ty = tid >> 4;   // c direction

    float acc[4][4] = {};

    const float* Vb = g_V + (size_t)b * CC * NN;
    const float* Pb = g_S + (size_t)b * NN * NN;

    const int r  = tid >> 2;
    const int k4 = tid & 3;

    for (int k0 = 0; k0 < NN; k0 += 16) {
        float4 a4 = *(const float4*)&Vb[(size_t)(c0 + r) * NN + k0 + k4 * 4];
        float4 b4 = *(const float4*)&Pb[(size_t)(n0 + r) * NN + k0 + k4 * 4];
        As[k4*4+0][r] = a4.x; As[k4*4+1][r] = a4.y; As[k4*4+2][r] = a4.z; As[k4*4+3][r] = a4.w;
        Bs[k4*4+0][r] = b4.x; Bs[k4*4+1][r] = b4.y; Bs[k4*4+2][r] = b4.z; Bs[k4*4+3][r] = b4.w;
        __syncthreads();

        #pragma unroll
        for (int kk = 0; kk < 16; kk++) {
            float4 af = *(const float4*)&As[kk][ty * 4];
            float4 bf = *(const float4*)&Bs[kk][tx * 4];
            float ar[4] = {af.x, af.y, af.z, af.w};
            float br[4] = {bf.x, bf.y, bf.z, bf.w};
            #pragma unroll
            for (int i = 0; i < 4; i++)
                #pragma unroll
                for (int j = 0; j < 4; j++)
                    acc[i][j] += ar[i] * br[j];
        }
        __syncthreads();
    }

    #pragma unroll
    for (int i = 0; i < 4; i++) {
        const int c = c0 + ty * 4 + i;
        const size_t base = ((size_t)b * CC + c) * NN + n0 + tx * 4;
        float4 xi = *(const float4*)&x[base];
        float4 o4 = make_float4(acc[i][0] + xi.x, acc[i][1] + xi.y,
                                acc[i][2] + xi.z, acc[i][3] + xi.w);
        *(float4*)&out[base] = o4;
    }
}

// ---------------------------------------------------------------------------
extern "C" void kernel_launch(void* const* d_in, const int* in_sizes, int n_in,
                              void* d_out, int out_size)
{
    const float* x  = (const float*)d_in[0];
    const float* Wq = (const float*)d_in[1];
    const float* bq = (const float*)d_in[2];
    const float* Wk = (const float*)d_in[3];
    const float* bk = (const float*)d_in[4];
    const float* Wv = (const float*)d_in[5];
    const float* bv = (const float*)d_in[6];
    float* out = (float*)d_out;

    dim3 blk(256);
    qkv_kernel   <<<dim3(NN / 64, CC / 64, BB), blk>>>(x, Wq, bq, Wk, bk, Wv, bv);
    scores_kernel<<<dim3(NN / 64, NN / 64, BB), blk>>>();
    softmax_kernel<<<BB * NN, 256>>>();
    out_kernel   <<<dim3(NN / 64, CC / 64, BB), blk>>>(x, out);
}

// round 2
// speedup vs baseline: 1.1629x; 1.1629x over previous
#include <cuda_runtime.h>

#define BB 8
#define CC 256
#define NN 2048

// Scratch (allocation-free: device globals)
__device__ float g_Qt[BB * NN * CC];            // [b][n][c]
__device__ float g_Kt[BB * NN * CC];            // [b][m][c]
__device__ float g_V [BB * CC * NN];            // [b][c][m]
__device__ float g_S [(size_t)BB * NN * NN];    // [b][n][m]

// ---------------------------------------------------------------------------
// Kernel 1: QKV projection (unchanged from passing R1 version).
// ---------------------------------------------------------------------------
__global__ __launch_bounds__(256) void qkv_kernel(
    const float* __restrict__ x,
    const float* __restrict__ Wq, const float* __restrict__ bq,
    const float* __restrict__ Wk, const float* __restrict__ bk,
    const float* __restrict__ Wv, const float* __restrict__ bv)
{
    __shared__ __align__(16) float xs [16][68];
    __shared__ __align__(16) float wqs[16][68];
    __shared__ __align__(16) float wks[16][68];
    __shared__ __align__(16) float wvs[16][68];

    const int n0 = blockIdx.x * 64;
    const int o0 = blockIdx.y * 64;
    const int b  = blockIdx.z;
    const int tid = threadIdx.x;
    const int tx = tid & 15;
    const int ty = tid >> 4;

    float aq[4][4] = {}, ak[4][4] = {}, av[4][4] = {};

    const float* xb = x + (size_t)b * CC * NN;

    for (int k0 = 0; k0 < CC; k0 += 16) {
        {
            const int kk = tid >> 4, j4 = tid & 15;
            float4 v = *(const float4*)&xb[(size_t)(k0 + kk) * NN + n0 + j4 * 4];
            *(float4*)&xs[kk][j4 * 4] = v;
        }
        {
            const int r = tid >> 2, k4 = tid & 3;
            const int wo = (o0 + r) * CC + k0 + k4 * 4;
            float4 q4 = *(const float4*)&Wq[wo];
            float4 k4v = *(const float4*)&Wk[wo];
            float4 v4 = *(const float4*)&Wv[wo];
            wqs[k4*4+0][r] = q4.x; wqs[k4*4+1][r] = q4.y; wqs[k4*4+2][r] = q4.z; wqs[k4*4+3][r] = q4.w;
            wks[k4*4+0][r] = k4v.x; wks[k4*4+1][r] = k4v.y; wks[k4*4+2][r] = k4v.z; wks[k4*4+3][r] = k4v.w;
            wvs[k4*4+0][r] = v4.x; wvs[k4*4+1][r] = v4.y; wvs[k4*4+2][r] = v4.z; wvs[k4*4+3][r] = v4.w;
        }
        __syncthreads();

        #pragma unroll
        for (int kk = 0; kk < 16; kk++) {
            float4 xf = *(const float4*)&xs [kk][tx * 4];
            float4 qf = *(const float4*)&wqs[kk][ty * 4];
            float4 kf = *(const float4*)&wks[kk][ty * 4];
            float4 vf = *(const float4*)&wvs[kk][ty * 4];
            float xr[4] = {xf.x, xf.y, xf.z, xf.w};
            float qr[4] = {qf.x, qf.y, qf.z, qf.w};
            float kr[4] = {kf.x, kf.y, kf.z, kf.w};
            float vr[4] = {vf.x, vf.y, vf.z, vf.w};
            #pragma unroll
            for (int i = 0; i < 4; i++)
                #pragma unroll
                for (int j = 0; j < 4; j++) {
                    aq[i][j] += qr[i] * xr[j];
                    ak[i][j] += kr[i] * xr[j];
                    av[i][j] += vr[i] * xr[j];
                }
        }
        __syncthreads();
    }

    float bqv[4], bkv[4], bvv[4];
    #pragma unroll
    for (int i = 0; i < 4; i++) {
        bqv[i] = bq[o0 + ty * 4 + i];
        bkv[i] = bk[o0 + ty * 4 + i];
        bvv[i] = bv[o0 + ty * 4 + i];
    }

    #pragma unroll
    for (int j = 0; j < 4; j++) {
        const int n = n0 + tx * 4 + j;
        const size_t base = ((size_t)b * NN + n) * CC + o0 + ty * 4;
        float4 q4 = make_float4(aq[0][j] + bqv[0], aq[1][j] + bqv[1],
                                aq[2][j] + bqv[2], aq[3][j] + bqv[3]);
        float4 k4 = make_float4(ak[0][j] + bkv[0], ak[1][j] + bkv[1],
                                ak[2][j] + bkv[2], ak[3][j] + bkv[3]);
        *(float4*)&g_Qt[base] = q4;
        *(float4*)&g_Kt[base] = k4;
    }
    #pragma unroll
    for (int i = 0; i < 4; i++) {
        const int o = o0 + ty * 4 + i;
        const size_t base = ((size_t)b * CC + o) * NN + n0 + tx * 4;
        float4 v4 = make_float4(av[i][0] + bvv[i], av[i][1] + bvv[i],
                                av[i][2] + bvv[i], av[i][3] + bvv[i]);
        *(float4*)&g_V[base] = v4;
    }
}

// ---------------------------------------------------------------------------
// 128x128 NT SGEMM, BK=16, 8x8 per thread, double-buffered smem.
// C[i][j] = (SCALE? scale:1) * sum_k A[i][k]*B[j][k]  (+ R[i][j] if RESID)
// A rows = C rows (i), B rows = C cols (j). Both strides = ld.
// ---------------------------------------------------------------------------
template<bool SCALE, bool RESID>
__global__ __launch_bounds__(256, 2) void gemm128(
    const float* __restrict__ A, const float* __restrict__ B,
    float* __restrict__ C, const float* __restrict__ R,
    int K, int ld, int ldc, float scale,
    size_t sA, size_t sB, size_t sC)
{
    __shared__ __align__(16) float As[2][16][132];
    __shared__ __align__(16) float Bs[2][16][132];

    const int j0 = blockIdx.x * 128;
    const int i0 = blockIdx.y * 128;
    const int b  = blockIdx.z;
    A += (size_t)b * sA;
    B += (size_t)b * sB;
    C += (size_t)b * sC;

    const int tid  = threadIdx.x;
    const int tx   = tid & 15;
    const int ty   = tid >> 4;
    const int lrow = tid >> 1;          // 0..127
    const int lseg = (tid & 1) * 8;     // 0 or 8

    const float* Ar = A + (size_t)(i0 + lrow) * ld + lseg;
    const float* Br = B + (size_t)(j0 + lrow) * ld + lseg;

    float acc[8][8] = {};

    // preload tile 0
    {
        float4 a0 = *(const float4*)(Ar + 0);
        float4 a1 = *(const float4*)(Ar + 4);
        float4 b0 = *(const float4*)(Br + 0);
        float4 b1 = *(const float4*)(Br + 4);
        As[0][lseg+0][lrow]=a0.x; As[0][lseg+1][lrow]=a0.y; As[0][lseg+2][lrow]=a0.z; As[0][lseg+3][lrow]=a0.w;
        As[0][lseg+4][lrow]=a1.x; As[0][lseg+5][lrow]=a1.y; As[0][lseg+6][lrow]=a1.z; As[0][lseg+7][lrow]=a1.w;
        Bs[0][lseg+0][lrow]=b0.x; Bs[0][lseg+1][lrow]=b0.y; Bs[0][lseg+2][lrow]=b0.z; Bs[0][lseg+3][lrow]=b0.w;
        Bs[0][lseg+4][lrow]=b1.x; Bs[0][lseg+5][lrow]=b1.y; Bs[0][lseg+6][lrow]=b1.z; Bs[0][lseg+7][lrow]=b1.w;
    }
    __syncthreads();

    const int NT = K >> 4;
    int buf = 0;
    for (int t = 0; t < NT; t++) {
        float4 pa0, pa1, pb0, pb1;
        const bool has_next = (t + 1 < NT);
        if (has_next) {
            const float* Ap = Ar + (t + 1) * 16;
            const float* Bp = Br + (t + 1) * 16;
            pa0 = *(const float4*)(Ap + 0);
            pa1 = *(const float4*)(Ap + 4);
            pb0 = *(const float4*)(Bp + 0);
            pb1 = *(const float4*)(Bp + 4);
        }

        #pragma unroll
        for (int kk = 0; kk < 16; kk++) {
            float4 af0 = *(const float4*)&As[buf][kk][ty * 4];
            float4 af1 = *(const float4*)&As[buf][kk][ty * 4 + 64];
            float4 bf0 = *(const float4*)&Bs[buf][kk][tx * 4];
            float4 bf1 = *(const float4*)&Bs[buf][kk][tx * 4 + 64];
            float a[8]  = {af0.x, af0.y, af0.z, af0.w, af1.x, af1.y, af1.z, af1.w};
            float bb[8] = {bf0.x, bf0.y, bf0.z, bf0.w, bf1.x, bf1.y, bf1.z, bf1.w};
            #pragma unroll
            for (int i = 0; i < 8; i++)
                #pragma unroll
                for (int j = 0; j < 8; j++)
                    acc[i][j] += a[i] * bb[j];
        }

        if (has_next) {
            const int nb = buf ^ 1;
            As[nb][lseg+0][lrow]=pa0.x; As[nb][lseg+1][lrow]=pa0.y; As[nb][lseg+2][lrow]=pa0.z; As[nb][lseg+3][lrow]=pa0.w;
            As[nb][lseg+4][lrow]=pa1.x; As[nb][lseg+5][lrow]=pa1.y; As[nb][lseg+6][lrow]=pa1.z; As[nb][lseg+7][lrow]=pa1.w;
            Bs[nb][lseg+0][lrow]=pb0.x; Bs[nb][lseg+1][lrow]=pb0.y; Bs[nb][lseg+2][lrow]=pb0.z; Bs[nb][lseg+3][lrow]=pb0.w;
            Bs[nb][lseg+4][lrow]=pb1.x; Bs[nb][lseg+5][lrow]=pb1.y; Bs[nb][lseg+6][lrow]=pb1.z; Bs[nb][lseg+7][lrow]=pb1.w;
        }
        __syncthreads();
        buf ^= 1;
    }

    // epilogue
    #pragma unroll
    for (int ih = 0; ih < 2; ih++)
    #pragma unroll
    for (int ii = 0; ii < 4; ii++) {
        const int i    = ty * 4 + ii + ih * 64;
        const int grow = i0 + i;
        #pragma unroll
        for (int jh = 0; jh < 2; jh++) {
            const int j   = tx * 4 + jh * 64;
            const size_t idx = (size_t)grow * ldc + j0 + j;
            float4 v = make_float4(acc[ih*4+ii][jh*4+0], acc[ih*4+ii][jh*4+1],
                                   acc[ih*4+ii][jh*4+2], acc[ih*4+ii][jh*4+3]);
            if (SCALE) { v.x *= scale; v.y *= scale; v.z *= scale; v.w *= scale; }
            if (RESID) {
                const float4 r = *(const float4*)&R[(size_t)b * sC + idx];
                v.x += r.x; v.y += r.y; v.z += r.z; v.w += r.w;
            }
            *(float4*)&C[idx] = v;
        }
    }
}

// ---------------------------------------------------------------------------
// Kernel 3: row softmax over m (2048 elems), in place on g_S (unchanged).
// ---------------------------------------------------------------------------
__global__ __launch_bounds__(256) void softmax_kernel()
{
    __shared__ float redmax[8];
    __shared__ float redsum[8];

    const size_t row = blockIdx.x;
    float* p = g_S + row * NN;
    const int tid  = threadIdx.x;
    const int lane = tid & 31;
    const int warp = tid >> 5;

    float v[8];
    float mx = -3.4e38f;
    #pragma unroll
    for (int t = 0; t < 8; t++) {
        v[t] = p[tid + t * 256];
        mx = fmaxf(mx, v[t]);
    }
    #pragma unroll
    for (int o = 16; o > 0; o >>= 1)
        mx = fmaxf(mx, __shfl_xor_sync(0xffffffffu, mx, o));
    if (lane == 0) redmax[warp] = mx;
    __syncthreads();
    if (warp == 0) {
        float w = (lane < 8) ? redmax[lane] : -3.4e38f;
        #pragma unroll
        for (int o = 4; o > 0; o >>= 1)
            w = fmaxf(w, __shfl_xor_sync(0xffffffffu, w, o));
        if (lane == 0) redmax[0] = w;
    }
    __syncthreads();
    mx = redmax[0];

    float s = 0.0f;
    #pragma unroll
    for (int t = 0; t < 8; t++) {
        v[t] = __expf(v[t] - mx);
        s += v[t];
    }
    #pragma unroll
    for (int o = 16; o > 0; o >>= 1)
        s += __shfl_xor_sync(0xffffffffu, s, o);
    if (lane == 0) redsum[warp] = s;
    __syncthreads();
    if (warp == 0) {
        float w = (lane < 8) ? redsum[lane] : 0.0f;
        #pragma unroll
        for (int o = 4; o > 0; o >>= 1)
            w += __shfl_xor_sync(0xffffffffu, w, o);
        if (lane == 0) redsum[0] = w;
    }
    __syncthreads();
    const float inv = 1.0f / redsum[0];

    #pragma unroll
    for (int t = 0; t < 8; t++)
        p[tid + t * 256] = v[t] * inv;
}

// ---------------------------------------------------------------------------
extern "C" void kernel_launch(void* const* d_in, const int* in_sizes, int n_in,
                              void* d_out, int out_size)
{
    const float* x  = (const float*)d_in[0];
    const float* Wq = (const float*)d_in[1];
    const float* bq = (const float*)d_in[2];
    const float* Wk = (const float*)d_in[3];
    const float* bk = (const float*)d_in[4];
    const float* Wv = (const float*)d_in[5];
    const float* bv = (const float*)d_in[6];
    float* out = (float*)d_out;

    void *pQt, *pKt, *pV, *pS;
    cudaGetSymbolAddress(&pQt, g_Qt);
    cudaGetSymbolAddress(&pKt, g_Kt);
    cudaGetSymbolAddress(&pV,  g_V);
    cudaGetSymbolAddress(&pS,  g_S);
    const float* Qt = (const float*)pQt;
    const float* Kt = (const float*)pKt;
    const float* V  = (const float*)pV;
    float* S = (float*)pS;

    dim3 blk(256);
    qkv_kernel<<<dim3(NN / 64, CC / 64, BB), blk>>>(x, Wq, bq, Wk, bk, Wv, bv);

    // scores: C=[n][m] 2048x2048, A=Qt rows n, B=Kt rows m, K=256
    gemm128<true, false><<<dim3(NN / 128, NN / 128, BB), blk>>>(
        Qt, Kt, S, nullptr,
        CC, CC, NN, 1.0f / 16.0f,
        (size_t)NN * CC, (size_t)NN * CC, (size_t)NN * NN);

    softmax_kernel<<<BB * NN, 256>>>();

    // out: C=[c][n] 256x2048, A=V rows c, B=P rows n, K=2048, +residual x
    gemm128<false, true><<<dim3(NN / 128, CC / 128, BB), blk>>>(
        V, S, out, x,
        NN, NN, NN, 1.0f,
        (size_t)CC * NN, (size_t)NN * NN, (size_t)CC * NN);
}

// round 4
// speedup vs baseline: 2.0427x; 1.7566x over previous
#include <cuda_runtime.h>
#include <cuda_bf16.h>
#include <cstdint>

#define BB 8
#define CC 256
#define NN 2048

// ---------------- scratch (device globals; no allocs) ----------------------
__device__ __nv_bfloat16 g_Qh[BB * NN * CC], g_Ql[BB * NN * CC];   // [b][n][c]
__device__ __nv_bfloat16 g_Kh[BB * NN * CC], g_Kl[BB * NN * CC];   // [b][m][c]
__device__ __nv_bfloat16 g_Vh[BB * CC * NN], g_Vl[BB * CC * NN];   // [b][c][m]
__device__ float         g_S [(size_t)BB * NN * NN];               // [b][n][m] fp32 scores
__device__ __nv_bfloat16 g_Ph[(size_t)BB * NN * NN];               // probs hi
__device__ __nv_bfloat16 g_Pl[(size_t)BB * NN * NN];               // probs lo

// ---------------- PTX helpers (baseline PTX only: sm_80-era) ----------------
__device__ __forceinline__ uint32_t smem_u32(const void* p) {
    uint32_t a;
    asm("{ .reg .u64 t; cvta.to.shared.u64 t, %1; cvt.u32.u64 %0, t; }"
        : "=r"(a) : "l"(p));
    return a;
}

#define CP_ASYNC16(dst, src) \
    asm volatile("cp.async.cg.shared.global [%0], [%1], 16;" \
                 :: "r"(dst), "l"(src) : "memory")
#define CP_COMMIT() asm volatile("cp.async.commit_group;" ::: "memory")
#define CP_WAIT(n)  asm volatile("cp.async.wait_group %0;" :: "n"(n) : "memory")

#define LDSM_X4(r0, r1, r2, r3, addr) \
    asm volatile("ldmatrix.sync.aligned.m8n8.x4.shared.b16 {%0,%1,%2,%3}, [%4];" \
                 : "=r"(r0), "=r"(r1), "=r"(r2), "=r"(r3) : "r"(addr))

#define MMA16816(c, a, b0, b1) \
    asm volatile("mma.sync.aligned.m16n8k16.row.col.f32.bf16.bf16.f32 " \
                 "{%0,%1,%2,%3}, {%4,%5,%6,%7}, {%8,%9}, {%0,%1,%2,%3};" \
                 : "+f"((c)[0]), "+f"((c)[1]), "+f"((c)[2]), "+f"((c)[3]) \
                 : "r"((a)[0]), "r"((a)[1]), "r"((a)[2]), "r"((a)[3]), \
                   "r"(b0), "r"(b1))

__device__ __forceinline__ __nv_bfloat16 bsplit_hi(float v) { return __float2bfloat16(v); }
__device__ __forceinline__ __nv_bfloat16 bsplit_lo(float v, __nv_bfloat16 h) {
    return __float2bfloat16(v - __bfloat162float(h));
}

// smem geometry: rows of 32 bf16 stored with 80-byte stride (conflict-free ldmatrix)
#define ROW_STRIDE 80
#define TILE_BYTES 10240            // 128 rows * 80 B
#define BUF_BYTES  40960            // Ah, Al, Bh, Bl
#define SMEM_TOTAL (2 * BUF_BYTES)  // double buffered

// ---------------------------------------------------------------------------
// Kernel 1: QKV projection (fp32 FFMA) -> bf16 hi/lo outputs.
// ---------------------------------------------------------------------------
__global__ __launch_bounds__(256) void qkv_kernel(
    const float* __restrict__ x,
    const float* __restrict__ Wq, const float* __restrict__ bq,
    const float* __restrict__ Wk, const float* __restrict__ bk,
    const float* __restrict__ Wv, const float* __restrict__ bv)
{
    __shared__ __align__(16) float xs [16][68];
    __shared__ __align__(16) float wqs[16][68];
    __shared__ __align__(16) float wks[16][68];
    __shared__ __align__(16) float wvs[16][68];

    const int n0 = blockIdx.x * 64;
    const int o0 = blockIdx.y * 64;
    const int b  = blockIdx.z;
    const int tid = threadIdx.x;
    const int tx = tid & 15;
    const int ty = tid >> 4;

    float aq[4][4] = {}, ak[4][4] = {}, av[4][4] = {};
    const float* xb = x + (size_t)b * CC * NN;

    for (int k0 = 0; k0 < CC; k0 += 16) {
        {
            const int kk = tid >> 4, j4 = tid & 15;
            float4 v = *(const float4*)&xb[(size_t)(k0 + kk) * NN + n0 + j4 * 4];
            *(float4*)&xs[kk][j4 * 4] = v;
        }
        {
            const int r = tid >> 2, k4 = tid & 3;
            const int wo = (o0 + r) * CC + k0 + k4 * 4;
            float4 q4 = *(const float4*)&Wq[wo];
            float4 k4v = *(const float4*)&Wk[wo];
            float4 v4 = *(const float4*)&Wv[wo];
            wqs[k4*4+0][r] = q4.x; wqs[k4*4+1][r] = q4.y; wqs[k4*4+2][r] = q4.z; wqs[k4*4+3][r] = q4.w;
            wks[k4*4+0][r] = k4v.x; wks[k4*4+1][r] = k4v.y; wks[k4*4+2][r] = k4v.z; wks[k4*4+3][r] = k4v.w;
            wvs[k4*4+0][r] = v4.x; wvs[k4*4+1][r] = v4.y; wvs[k4*4+2][r] = v4.z; wvs[k4*4+3][r] = v4.w;
        }
        __syncthreads();

        #pragma unroll
        for (int kk = 0; kk < 16; kk++) {
            float4 xf = *(const float4*)&xs [kk][tx * 4];
            float4 qf = *(const float4*)&wqs[kk][ty * 4];
            float4 kf = *(const float4*)&wks[kk][ty * 4];
            float4 vf = *(const float4*)&wvs[kk][ty * 4];
            float xr[4] = {xf.x, xf.y, xf.z, xf.w};
            float qr[4] = {qf.x, qf.y, qf.z, qf.w};
            float kr[4] = {kf.x, kf.y, kf.z, kf.w};
            float vr[4] = {vf.x, vf.y, vf.z, vf.w};
            #pragma unroll
            for (int i = 0; i < 4; i++)
                #pragma unroll
                for (int j = 0; j < 4; j++) {
                    aq[i][j] += qr[i] * xr[j];
                    ak[i][j] += kr[i] * xr[j];
                    av[i][j] += vr[i] * xr[j];
                }
        }
        __syncthreads();
    }

    float bqv[4], bkv[4], bvv[4];
    #pragma unroll
    for (int i = 0; i < 4; i++) {
        bqv[i] = bq[o0 + ty * 4 + i];
        bkv[i] = bk[o0 + ty * 4 + i];
        bvv[i] = bv[o0 + ty * 4 + i];
    }

    #pragma unroll
    for (int j = 0; j < 4; j++) {
        const int n = n0 + tx * 4 + j;
        const size_t base = ((size_t)b * NN + n) * CC + o0 + ty * 4;
        __nv_bfloat16 qh[4], ql[4], kh[4], kl[4];
        #pragma unroll
        for (int i = 0; i < 4; i++) {
            float q = aq[i][j] + bqv[i];
            float k = ak[i][j] + bkv[i];
            qh[i] = bsplit_hi(q); ql[i] = bsplit_lo(q, qh[i]);
            kh[i] = bsplit_hi(k); kl[i] = bsplit_lo(k, kh[i]);
        }
        *(__nv_bfloat162*)&g_Qh[base]     = __halves2bfloat162(qh[0], qh[1]);
        *(__nv_bfloat162*)&g_Qh[base + 2] = __halves2bfloat162(qh[2], qh[3]);
        *(__nv_bfloat162*)&g_Ql[base]     = __halves2bfloat162(ql[0], ql[1]);
        *(__nv_bfloat162*)&g_Ql[base + 2] = __halves2bfloat162(ql[2], ql[3]);
        *(__nv_bfloat162*)&g_Kh[base]     = __halves2bfloat162(kh[0], kh[1]);
        *(__nv_bfloat162*)&g_Kh[base + 2] = __halves2bfloat162(kh[2], kh[3]);
        *(__nv_bfloat162*)&g_Kl[base]     = __halves2bfloat162(kl[0], kl[1]);
        *(__nv_bfloat162*)&g_Kl[base + 2] = __halves2bfloat162(kl[2], kl[3]);
    }
    #pragma unroll
    for (int i = 0; i < 4; i++) {
        const int o = o0 + ty * 4 + i;
        const size_t base = ((size_t)b * CC + o) * NN + n0 + tx * 4;
        __nv_bfloat16 vh[4], vl[4];
        #pragma unroll
        for (int j = 0; j < 4; j++) {
            float v = av[i][j] + bvv[i];
            vh[j] = bsplit_hi(v); vl[j] = bsplit_lo(v, vh[j]);
        }
        *(__nv_bfloat162*)&g_Vh[base]     = __halves2bfloat162(vh[0], vh[1]);
        *(__nv_bfloat162*)&g_Vh[base + 2] = __halves2bfloat162(vh[2], vh[3]);
        *(__nv_bfloat162*)&g_Vl[base]     = __halves2bfloat162(vl[0], vl[1]);
        *(__nv_bfloat162*)&g_Vl[base + 2] = __halves2bfloat162(vl[2], vl[3]);
    }
}

// ---------------------------------------------------------------------------
// NT GEMM on HMMA (mma.sync bf16, fp32 acc) with hi/lo 3-pass split.
//   C[i][j] = s * sum_k A[i][k]*B[j][k]  (+ R[i][j])
// CTA: 128x128 tile, 256 thr (8 warps 2x4), warp 64x32. BK=32, cp.async x2buf.
// ---------------------------------------------------------------------------
template<int KTILES, bool SCALE, bool RESID>
__global__ __launch_bounds__(256) void mma_gemm(
    const __nv_bfloat16* __restrict__ Ah, const __nv_bfloat16* __restrict__ Al,
    const __nv_bfloat16* __restrict__ Bh, const __nv_bfloat16* __restrict__ Bl,
    float* __restrict__ C, const float* __restrict__ R,
    int lda, int ldb, int ldc, float scale,
    size_t sA, size_t sB, size_t sC)
{
    extern __shared__ __align__(16) char sm[];

    const int j0 = blockIdx.x * 128;
    const int i0 = blockIdx.y * 128;
    const int b  = blockIdx.z;

    const int tid  = threadIdx.x;
    const int wid  = tid >> 5;
    const int lane = tid & 31;
    const int wm   = wid >> 2;        // 0..1 (m)
    const int wn   = wid & 3;         // 0..3 (n)

    const __nv_bfloat16* gAh = Ah + (size_t)b * sA;
    const __nv_bfloat16* gAl = Al + (size_t)b * sA;
    const __nv_bfloat16* gBh = Bh + (size_t)b * sB;
    const __nv_bfloat16* gBl = Bl + (size_t)b * sB;

    // cp.async geometry: 2 threads per row, each thread 2 chunks of 8 bf16
    const int lr = tid >> 1;
    const int lc = (tid & 1) * 2;
    const uint32_t smbase = smem_u32(sm);

    // ldmatrix per-lane offsets
    const uint32_t offA = (uint32_t)((lane & 15) * ROW_STRIDE + (lane >> 4) * 16);
    const uint32_t offB = (uint32_t)(((lane & 7) + ((lane >> 4) << 3)) * ROW_STRIDE
                                     + (((lane >> 3) & 1) << 4));

    float acc[4][4][4] = {};   // [mt][nt][reg]

    auto issue = [&](int buf, int k0) {
        const uint32_t base = smbase + buf * BUF_BYTES;
        #pragma unroll
        for (int c = 0; c < 2; c++) {
            const int chunk = lc + c;
            const uint32_t so = base + (uint32_t)(lr * ROW_STRIDE + chunk * 16);
            const size_t gca = (size_t)(i0 + lr) * lda + k0 + chunk * 8;
            const size_t gcb = (size_t)(j0 + lr) * ldb + k0 + chunk * 8;
            CP_ASYNC16(so,                  gAh + gca);
            CP_ASYNC16(so + TILE_BYTES,     gAl + gca);
            CP_ASYNC16(so + 2 * TILE_BYTES, gBh + gcb);
            CP_ASYNC16(so + 3 * TILE_BYTES, gBl + gcb);
        }
        CP_COMMIT();
    };

    issue(0, 0);
    issue(1, 32);

    #pragma unroll 1
    for (int t = 0; t < KTILES; t++) {
        if (t == KTILES - 1) { CP_WAIT(0); } else { CP_WAIT(1); }
        __syncthreads();

        const uint32_t base = smbase + (t & 1) * BUF_BYTES;
        const uint32_t aAh = base;
        const uint32_t aAl = base + TILE_BYTES;
        const uint32_t aBh = base + 2 * TILE_BYTES;
        const uint32_t aBl = base + 3 * TILE_BYTES;

        #pragma unroll
        for (int ks = 0; ks < 2; ks++) {
            const uint32_t kb2 = ks * 32;   // kb * 2 bytes (kb = 16*ks)

            uint32_t ahf[4][4], alf[4][4];
            #pragma unroll
            for (int mt = 0; mt < 4; mt++) {
                const uint32_t toff = (uint32_t)((wm * 64 + mt * 16) * ROW_STRIDE) + kb2 + offA;
                LDSM_X4(ahf[mt][0], ahf[mt][1], ahf[mt][2], ahf[mt][3], aAh + toff);
                LDSM_X4(alf[mt][0], alf[mt][1], alf[mt][2], alf[mt][3], aAl + toff);
            }
            uint32_t bhf[4][2], blf[4][2];
            #pragma unroll
            for (int g = 0; g < 2; g++) {
                const uint32_t toff = (uint32_t)((wn * 32 + g * 16) * ROW_STRIDE) + kb2 + offB;
                LDSM_X4(bhf[2*g][0], bhf[2*g][1], bhf[2*g+1][0], bhf[2*g+1][1], aBh + toff);
                LDSM_X4(blf[2*g][0], blf[2*g][1], blf[2*g+1][0], blf[2*g+1][1], aBl + toff);
            }

            #pragma unroll
            for (int mt = 0; mt < 4; mt++)
                #pragma unroll
                for (int nt = 0; nt < 4; nt++)
                    MMA16816(acc[mt][nt], ahf[mt], bhf[nt][0], bhf[nt][1]);
            #pragma unroll
            for (int mt = 0; mt < 4; mt++)
                #pragma unroll
                for (int nt = 0; nt < 4; nt++)
                    MMA16816(acc[mt][nt], ahf[mt], blf[nt][0], blf[nt][1]);
            #pragma unroll
            for (int mt = 0; mt < 4; mt++)
                #pragma unroll
                for (int nt = 0; nt < 4; nt++)
                    MMA16816(acc[mt][nt], alf[mt], bhf[nt][0], bhf[nt][1]);
        }

        __syncthreads();
        if (t + 2 < KTILES) issue(t & 1, (t + 2) * 32);
    }

    // epilogue
    const int g  = lane >> 2;
    const int tq = lane & 3;
    float* Cb = C + (size_t)b * sC;
    const float* Rb = R + (size_t)b * sC;

    #pragma unroll
    for (int mt = 0; mt < 4; mt++) {
        const int row0 = i0 + wm * 64 + mt * 16 + g;
        #pragma unroll
        for (int nt = 0; nt < 4; nt++) {
            const int col = j0 + wn * 32 + nt * 8 + tq * 2;
            float2 v0 = make_float2(acc[mt][nt][0], acc[mt][nt][1]);
            float2 v1 = make_float2(acc[mt][nt][2], acc[mt][nt][3]);
            if (SCALE) { v0.x *= scale; v0.y *= scale; v1.x *= scale; v1.y *= scale; }
            const size_t idx0 = (size_t)row0 * ldc + col;
            const size_t idx1 = (size_t)(row0 + 8) * ldc + col;
            if (RESID) {
                float2 r0 = *(const float2*)&Rb[idx0];
                float2 r1 = *(const float2*)&Rb[idx1];
                v0.x += r0.x; v0.y += r0.y; v1.x += r1.x; v1.y += r1.y;
            }
            *(float2*)&Cb[idx0] = v0;
            *(float2*)&Cb[idx1] = v1;
        }
    }
}

// ---------------------------------------------------------------------------
// Kernel 3: row softmax over m, fp32 scores -> bf16 hi/lo probs.
// ---------------------------------------------------------------------------
__global__ __launch_bounds__(256) void softmax_kernel()
{
    __shared__ float redmax[8];
    __shared__ float redsum[8];

    const size_t row = blockIdx.x;
    const float* p = g_S + row * NN;
    __nv_bfloat16* ph = g_Ph + row * NN;
    __nv_bfloat16* pl = g_Pl + row * NN;
    const int tid  = threadIdx.x;
    const int lane = tid & 31;
    const int warp = tid >> 5;

    float v[8];
    float mx = -3.4e38f;
    #pragma unroll
    for (int t = 0; t < 8; t++) {
        v[t] = p[tid + t * 256];
        mx = fmaxf(mx, v[t]);
    }
    #pragma unroll
    for (int o = 16; o > 0; o >>= 1)
        mx = fmaxf(mx, __shfl_xor_sync(0xffffffffu, mx, o));
    if (lane == 0) redmax[warp] = mx;
    __syncthreads();
    if (warp == 0) {
        float w = (lane < 8) ? redmax[lane] : -3.4e38f;
        #pragma unroll
        for (int o = 4; o > 0; o >>= 1)
            w = fmaxf(w, __shfl_xor_sync(0xffffffffu, w, o));
        if (lane == 0) redmax[0] = w;
    }
    __syncthreads();
    mx = redmax[0];

    float s = 0.0f;
    #pragma unroll
    for (int t = 0; t < 8; t++) {
        v[t] = __expf(v[t] - mx);
        s += v[t];
    }
    #pragma unroll
    for (int o = 16; o > 0; o >>= 1)
        s += __shfl_xor_sync(0xffffffffu, s, o);
    if (lane == 0) redsum[warp] = s;
    __syncthreads();
    if (warp == 0) {
        float w = (lane < 8) ? redsum[lane] : 0.0f;
        #pragma unroll
        for (int o = 4; o > 0; o >>= 1)
            w += __shfl_xor_sync(0xffffffffu, w, o);
        if (lane == 0) redsum[0] = w;
    }
    __syncthreads();
    const float inv = 1.0f / redsum[0];

    #pragma unroll
    for (int t = 0; t < 8; t++) {
        const float val = v[t] * inv;
        const __nv_bfloat16 h = bsplit_hi(val);
        ph[tid + t * 256] = h;
        pl[tid + t * 256] = bsplit_lo(val, h);
    }
}

// ---------------------------------------------------------------------------
extern "C" void kernel_launch(void* const* d_in, const int* in_sizes, int n_in,
                              void* d_out, int out_size)
{
    const float* x  = (const float*)d_in[0];
    const float* Wq = (const float*)d_in[1];
    const float* bq = (const float*)d_in[2];
    const float* Wk = (const float*)d_in[3];
    const float* bk = (const float*)d_in[4];
    const float* Wv = (const float*)d_in[5];
    const float* bv = (const float*)d_in[6];
    float* out = (float*)d_out;

    void *pQh, *pQl, *pKh, *pKl, *pVh, *pVl, *pS, *pPh, *pPl;
    cudaGetSymbolAddress(&pQh, g_Qh); cudaGetSymbolAddress(&pQl, g_Ql);
    cudaGetSymbolAddress(&pKh, g_Kh); cudaGetSymbolAddress(&pKl, g_Kl);
    cudaGetSymbolAddress(&pVh, g_Vh); cudaGetSymbolAddress(&pVl, g_Vl);
    cudaGetSymbolAddress(&pS,  g_S);
    cudaGetSymbolAddress(&pPh, g_Ph); cudaGetSymbolAddress(&pPl, g_Pl);

    cudaFuncSetAttribute(mma_gemm<CC / 32, true, false>,
                         cudaFuncAttributeMaxDynamicSharedMemorySize, SMEM_TOTAL);
    cudaFuncSetAttribute(mma_gemm<NN / 32, false, true>,
                         cudaFuncAttributeMaxDynamicSharedMemorySize, SMEM_TOTAL);

    dim3 blk(256);
    qkv_kernel<<<dim3(NN / 64, CC / 64, BB), blk>>>(x, Wq, bq, Wk, bk, Wv, bv);

    // scores: C[n][m] = 1/16 * Qt[n][:] . Kt[m][:]   (K=256)
    mma_gemm<CC / 32, true, false><<<dim3(NN / 128, NN / 128, BB), blk, SMEM_TOTAL>>>(
        (const __nv_bfloat16*)pQh, (const __nv_bfloat16*)pQl,
        (const __nv_bfloat16*)pKh, (const __nv_bfloat16*)pKl,
        (float*)pS, nullptr,
        CC, CC, NN, 1.0f / 16.0f,
        (size_t)NN * CC, (size_t)NN * CC, (size_t)NN * NN);

    softmax_kernel<<<BB * NN, 256>>>();

    // out: C[c][n] = V[c][:] . P[n][:]  (K=2048) + x
    mma_gemm<NN / 32, false, true><<<dim3(NN / 128, CC / 128, BB), blk, SMEM_TOTAL>>>(
        (const __nv_bfloat16*)pVh, (const __nv_bfloat16*)pVl,
        (const __nv_bfloat16*)pPh, (const __nv_bfloat16*)pPl,
        out, x,
        NN, NN, NN, 1.0f,
        (size_t)CC * NN, (size_t)NN * NN, (size_t)CC * NN);
}

// round 5
// speedup vs baseline: 2.3423x; 1.1467x over previous
#include <cuda_runtime.h>
#include <cuda_bf16.h>
#include <cstdint>

#define BB 8
#define CC 256
#define NN 2048

// ---------------- scratch (device globals; no allocs) ----------------------
__device__ __nv_bfloat16 g_Xh[BB * NN * CC], g_Xl[BB * NN * CC];   // xT [b][n][c]
__device__ __nv_bfloat16 g_Wh[3 * CC * CC],  g_Wl[3 * CC * CC];    // Wq,Wk,Wv split
__device__ __nv_bfloat16 g_Qh[BB * NN * CC], g_Ql[BB * NN * CC];   // [b][n][c]
__device__ __nv_bfloat16 g_Kh[BB * NN * CC], g_Kl[BB * NN * CC];   // [b][m][c]
__device__ __nv_bfloat16 g_Vh[BB * CC * NN], g_Vl[BB * CC * NN];   // [b][c][m]
__device__ float         g_S [(size_t)BB * NN * NN];               // fp32 scores
__device__ __nv_bfloat16 g_Ph[(size_t)BB * NN * NN];               // probs hi
__device__ __nv_bfloat16 g_Pl[(size_t)BB * NN * NN];               // probs lo

// ---------------- PTX helpers (baseline PTX only) ---------------------------
__device__ __forceinline__ uint32_t smem_u32(const void* p) {
    uint32_t a;
    asm("{ .reg .u64 t; cvta.to.shared.u64 t, %1; cvt.u32.u64 %0, t; }"
        : "=r"(a) : "l"(p));
    return a;
}

#define CP_ASYNC16(dst, src) \
    asm volatile("cp.async.cg.shared.global [%0], [%1], 16;" \
                 :: "r"(dst), "l"(src) : "memory")
#define CP_COMMIT() asm volatile("cp.async.commit_group;" ::: "memory")
#define CP_WAIT(n)  asm volatile("cp.async.wait_group %0;" :: "n"(n) : "memory")

#define LDSM_X4(r0, r1, r2, r3, addr) \
    asm volatile("ldmatrix.sync.aligned.m8n8.x4.shared.b16 {%0,%1,%2,%3}, [%4];" \
                 : "=r"(r0), "=r"(r1), "=r"(r2), "=r"(r3) : "r"(addr))

#define MMA16816(c, a, b0, b1) \
    asm volatile("mma.sync.aligned.m16n8k16.row.col.f32.bf16.bf16.f32 " \
                 "{%0,%1,%2,%3}, {%4,%5,%6,%7}, {%8,%9}, {%0,%1,%2,%3};" \
                 : "+f"((c)[0]), "+f"((c)[1]), "+f"((c)[2]), "+f"((c)[3]) \
                 : "r"((a)[0]), "r"((a)[1]), "r"((a)[2]), "r"((a)[3]), \
                   "r"(b0), "r"(b1))

__device__ __forceinline__ __nv_bfloat16 bsplit_hi(float v) { return __float2bfloat16(v); }
__device__ __forceinline__ __nv_bfloat16 bsplit_lo(float v, __nv_bfloat16 h) {
    return __float2bfloat16(v - __bfloat162float(h));
}

// smem geometry: rows of 32 bf16, 80-byte stride (conflict-free ldmatrix)
#define ROW_STRIDE 80
#define TILE_BYTES 10240            // 128 rows * 80 B
#define BUF_BYTES  40960            // Ah, Al, Bh, Bl
#define SMEM_TOTAL (2 * BUF_BYTES)

// qkv kernel smem: A hi/lo (128 rows) + 6 W tiles (64 rows)
#define QB_TILE    5120             // 64 * 80
#define QBUF       (2 * TILE_BYTES + 6 * QB_TILE)   // 51200
#define QSMEM      (2 * QBUF)                       // 102400

// ---------------------------------------------------------------------------
// xsplit: x [b][c][n] fp32 -> xT hi/lo [b][n][c] bf16  (32x32 tiled transpose)
// ---------------------------------------------------------------------------
__global__ __launch_bounds__(256) void xsplit_kernel(const float* __restrict__ x)
{
    __shared__ float t[32][33];
    const int n0 = blockIdx.x * 32;
    const int c0 = blockIdx.y * 32;
    const int b  = blockIdx.z;
    const int tx = threadIdx.x & 31;
    const int ty = threadIdx.x >> 5;     // 0..7

    #pragma unroll
    for (int k = 0; k < 4; k++)
        t[ty + k * 8][tx] = x[((size_t)b * CC + c0 + ty + k * 8) * NN + n0 + tx];
    __syncthreads();
    #pragma unroll
    for (int k = 0; k < 4; k++) {
        const float v = t[tx][ty + k * 8];
        const __nv_bfloat16 h = bsplit_hi(v);
        const size_t idx = ((size_t)b * NN + n0 + ty + k * 8) * CC + c0 + tx;
        g_Xh[idx] = h;
        g_Xl[idx] = bsplit_lo(v, h);
    }
}

// ---------------------------------------------------------------------------
// wsplit: Wq/Wk/Wv fp32 -> g_Wh/g_Wl  (layout [mat][o][c])
// ---------------------------------------------------------------------------
__global__ __launch_bounds__(256) void wsplit_kernel(
    const float* __restrict__ Wq, const float* __restrict__ Wk,
    const float* __restrict__ Wv)
{
    const int m = blockIdx.y;
    const int e = blockIdx.x * 256 + threadIdx.x;     // 0..65535
    const float v = (m == 0 ? Wq : (m == 1 ? Wk : Wv))[e];
    const __nv_bfloat16 h = bsplit_hi(v);
    g_Wh[m * CC * CC + e] = h;
    g_Wl[m * CC * CC + e] = bsplit_lo(v, h);
}

// ---------------------------------------------------------------------------
// qkv_mma: C[n][o] = sum_c xT[n][c] * W[o][c]  for Q,K,V at once (HMMA 3-pass).
// CTA tile 128n x 64o, 8 warps (wm=wid>>1 over n, wn=wid&1 over o), warp 32x32.
// Epilogue: +bias, split; Q/K -> [n][c]; V transposed via smem -> [c][n].
// ---------------------------------------------------------------------------
__global__ __launch_bounds__(256) void qkv_mma(
    const float* __restrict__ bq, const float* __restrict__ bk,
    const float* __restrict__ bv)
{
    extern __shared__ __align__(16) char sm[];
    const int n0 = blockIdx.x * 128;
    const int o0 = blockIdx.y * 64;
    const int b  = blockIdx.z;

    const int tid  = threadIdx.x;
    const int wid  = tid >> 5;
    const int lane = tid & 31;
    const int wn   = wid & 1;         // o dir
    const int wm   = wid >> 1;        // n dir (0..3)

    const uint32_t smbase = smem_u32(sm);

    const __nv_bfloat16* gXh = g_Xh + ((size_t)b * NN + n0) * CC;
    const __nv_bfloat16* gXl = g_Xl + ((size_t)b * NN + n0) * CC;
    const __nv_bfloat16* W6[6] = {
        g_Wh,               g_Wl,
        g_Wh + CC * CC,     g_Wl + CC * CC,
        g_Wh + 2 * CC * CC, g_Wl + 2 * CC * CC };

    const uint32_t offA = (uint32_t)((lane & 15) * ROW_STRIDE + (lane >> 4) * 16);
    const uint32_t offB = (uint32_t)(((lane & 7) + ((lane >> 4) << 3)) * ROW_STRIDE
                                     + (((lane >> 3) & 1) << 4));

    float acc[3][2][4][4] = {};   // [qkv][mt][nt][reg]

    // load geometry: A 128 rows, 2 thr/row, 2 chunks each; B 64 rows, 4 thr/row
    const int alr = tid >> 1, alc = (tid & 1) * 2;
    const int brb = tid >> 2, bcb = tid & 3;

    auto issue = [&](int buf, int k0) {
        const uint32_t base = smbase + buf * QBUF;
        #pragma unroll
        for (int c = 0; c < 2; c++) {
            const int chunk = alc + c;
            const uint32_t so = base + (uint32_t)(alr * ROW_STRIDE + chunk * 16);
            const size_t gofs = (size_t)alr * CC + k0 + chunk * 8;
            CP_ASYNC16(so,              gXh + gofs);
            CP_ASYNC16(so + TILE_BYTES, gXl + gofs);
        }
        const uint32_t sob = base + 2 * TILE_BYTES
                           + (uint32_t)(brb * ROW_STRIDE + bcb * 16);
        const size_t gwb = (size_t)(o0 + brb) * CC + k0 + bcb * 8;
        #pragma unroll
        for (int m = 0; m < 6; m++)
            CP_ASYNC16(sob + m * QB_TILE, W6[m] + gwb);
        CP_COMMIT();
    };

    issue(0, 0);
    issue(1, 32);

    #pragma unroll 1
    for (int t = 0; t < 8; t++) {
        if (t == 7) { CP_WAIT(0); } else { CP_WAIT(1); }
        __syncthreads();
        const uint32_t base = smbase + (t & 1) * QBUF;

        #pragma unroll
        for (int ks = 0; ks < 2; ks++) {
            const uint32_t kb2 = ks * 32;
            uint32_t ah[2][4], al[2][4];
            #pragma unroll
            for (int mt = 0; mt < 2; mt++) {
                const uint32_t toff = (uint32_t)((wm * 32 + mt * 16) * ROW_STRIDE) + kb2 + offA;
                LDSM_X4(ah[mt][0], ah[mt][1], ah[mt][2], ah[mt][3], base + toff);
                LDSM_X4(al[mt][0], al[mt][1], al[mt][2], al[mt][3], base + TILE_BYTES + toff);
            }
            #pragma unroll
            for (int q = 0; q < 3; q++) {
                uint32_t bh[4][2], bl[4][2];
                #pragma unroll
                for (int g = 0; g < 2; g++) {
                    const uint32_t toffb = (uint32_t)((wn * 32 + g * 16) * ROW_STRIDE) + kb2 + offB;
                    const uint32_t bbh = base + 2 * TILE_BYTES + (2 * q)     * QB_TILE + toffb;
                    const uint32_t bbl = base + 2 * TILE_BYTES + (2 * q + 1) * QB_TILE + toffb;
                    LDSM_X4(bh[2*g][0], bh[2*g][1], bh[2*g+1][0], bh[2*g+1][1], bbh);
                    LDSM_X4(bl[2*g][0], bl[2*g][1], bl[2*g+1][0], bl[2*g+1][1], bbl);
                }
                #pragma unroll
                for (int mt = 0; mt < 2; mt++)
                    #pragma unroll
                    for (int nt = 0; nt < 4; nt++) {
                        MMA16816(acc[q][mt][nt], ah[mt], bh[nt][0], bh[nt][1]);
                        MMA16816(acc[q][mt][nt], ah[mt], bl[nt][0], bl[nt][1]);
                        MMA16816(acc[q][mt][nt], al[mt], bh[nt][0], bh[nt][1]);
                    }
            }
        }
        __syncthreads();
        if (t + 2 < 8) issue(t & 1, (t + 2) * 32);
    }

    const int g  = lane >> 2;
    const int tq = lane & 3;

    // ---- Q, K: direct [n][c] stores with bias + split ----
    #pragma unroll
    for (int mt = 0; mt < 2; mt++)
        #pragma unroll
        for (int h = 0; h < 2; h++) {
            const int n = n0 + wm * 32 + mt * 16 + g + h * 8;
            #pragma unroll
            for (int nt = 0; nt < 4; nt++) {
                const int col = o0 + wn * 32 + nt * 8 + tq * 2;
                const size_t idx = ((size_t)b * NN + n) * CC + col;
                const float q0 = acc[0][mt][nt][2*h]   + bq[col];
                const float q1 = acc[0][mt][nt][2*h+1] + bq[col + 1];
                const float k0v = acc[1][mt][nt][2*h]   + bk[col];
                const float k1v = acc[1][mt][nt][2*h+1] + bk[col + 1];
                const __nv_bfloat16 qh0 = bsplit_hi(q0), qh1 = bsplit_hi(q1);
                const __nv_bfloat16 kh0 = bsplit_hi(k0v), kh1 = bsplit_hi(k1v);
                *(__nv_bfloat162*)&g_Qh[idx] = __halves2bfloat162(qh0, qh1);
                *(__nv_bfloat162*)&g_Ql[idx] = __halves2bfloat162(bsplit_lo(q0, qh0), bsplit_lo(q1, qh1));
                *(__nv_bfloat162*)&g_Kh[idx] = __halves2bfloat162(kh0, kh1);
                *(__nv_bfloat162*)&g_Kl[idx] = __halves2bfloat162(bsplit_lo(k0v, kh0), bsplit_lo(k1v, kh1));
            }
        }

    // ---- V: stage fp32 in smem, transpose to [c][n] ----
    __syncthreads();                       // done with pipeline smem
    float* vbuf = (float*)sm;              // [128][65]
    #pragma unroll
    for (int mt = 0; mt < 2; mt++)
        #pragma unroll
        for (int h = 0; h < 2; h++) {
            const int row = wm * 32 + mt * 16 + g + h * 8;
            #pragma unroll
            for (int nt = 0; nt < 4; nt++) {
                const int col = wn * 32 + nt * 8 + tq * 2;
                vbuf[row * 65 + col]     = acc[2][mt][nt][2*h]   + bv[o0 + col];
                vbuf[row * 65 + col + 1] = acc[2][mt][nt][2*h+1] + bv[o0 + col + 1];
            }
        }
    __syncthreads();
    #pragma unroll
    for (int cr = 0; cr < 8; cr++) {
        const int c = wid * 8 + cr;
        const size_t obase = ((size_t)b * CC + o0 + c) * NN + n0;
        #pragma unroll
        for (int it = 0; it < 2; it++) {
            const int nl = it * 64 + lane * 2;
            const float f0 = vbuf[nl * 65 + c];
            const float f1 = vbuf[(nl + 1) * 65 + c];
            const __nv_bfloat16 h0 = bsplit_hi(f0), h1 = bsplit_hi(f1);
            *(__nv_bfloat162*)&g_Vh[obase + nl] = __halves2bfloat162(h0, h1);
            *(__nv_bfloat162*)&g_Vl[obase + nl] = __halves2bfloat162(bsplit_lo(f0, h0), bsplit_lo(f1, h1));
        }
    }
}

// ---------------------------------------------------------------------------
// NT GEMM on HMMA (bf16 3-pass) — unchanged proven kernel.
// ---------------------------------------------------------------------------
template<int KTILES, bool SCALE, bool RESID>
__global__ __launch_bounds__(256) void mma_gemm(
    const __nv_bfloat16* __restrict__ Ah, const __nv_bfloat16* __restrict__ Al,
    const __nv_bfloat16* __restrict__ Bh, const __nv_bfloat16* __restrict__ Bl,
    float* __restrict__ C, const float* __restrict__ R,
    int lda, int ldb, int ldc, float scale,
    size_t sA, size_t sB, size_t sC)
{
    extern __shared__ __align__(16) char sm[];

    const int j0 = blockIdx.x * 128;
    const int i0 = blockIdx.y * 128;
    const int b  = blockIdx.z;

    const int tid  = threadIdx.x;
    const int lane = tid & 31;
    const int wid  = tid >> 5;
    const int wm   = wid >> 2;
    const int wn   = wid & 3;

    const __nv_bfloat16* gAh = Ah + (size_t)b * sA;
    const __nv_bfloat16* gAl = Al + (size_t)b * sA;
    const __nv_bfloat16* gBh = Bh + (size_t)b * sB;
    const __nv_bfloat16* gBl = Bl + (size_t)b * sB;

    const int lr = tid >> 1;
    const int lc = (tid & 1) * 2;
    const uint32_t smbase = smem_u32(sm);

    const uint32_t offA = (uint32_t)((lane & 15) * ROW_STRIDE + (lane >> 4) * 16);
    const uint32_t offB = (uint32_t)(((lane & 7) + ((lane >> 4) << 3)) * ROW_STRIDE
                                     + (((lane >> 3) & 1) << 4));

    float acc[4][4][4] = {};

    auto issue = [&](int buf, int k0) {
        const uint32_t base = smbase + buf * BUF_BYTES;
        #pragma unroll
        for (int c = 0; c < 2; c++) {
            const int chunk = lc + c;
            const uint32_t so = base + (uint32_t)(lr * ROW_STRIDE + chunk * 16);
            const size_t gca = (size_t)(i0 + lr) * lda + k0 + chunk * 8;
            const size_t gcb = (size_t)(j0 + lr) * ldb + k0 + chunk * 8;
            CP_ASYNC16(so,                  gAh + gca);
            CP_ASYNC16(so + TILE_BYTES,     gAl + gca);
            CP_ASYNC16(so + 2 * TILE_BYTES, gBh + gcb);
            CP_ASYNC16(so + 3 * TILE_BYTES, gBl + gcb);
        }
        CP_COMMIT();
    };

    issue(0, 0);
    issue(1, 32);

    #pragma unroll 1
    for (int t = 0; t < KTILES; t++) {
        if (t == KTILES - 1) { CP_WAIT(0); } else { CP_WAIT(1); }
        __syncthreads();

        const uint32_t base = smbase + (t & 1) * BUF_BYTES;
        const uint32_t aAh = base;
        const uint32_t aAl = base + TILE_BYTES;
        const uint32_t aBh = base + 2 * TILE_BYTES;
        const uint32_t aBl = base + 3 * TILE_BYTES;

        #pragma unroll
        for (int ks = 0; ks < 2; ks++) {
            const uint32_t kb2 = ks * 32;

            uint32_t ahf[4][4], alf[4][4];
            #pragma unroll
            for (int mt = 0; mt < 4; mt++) {
                const uint32_t toff = (uint32_t)((wm * 64 + mt * 16) * ROW_STRIDE) + kb2 + offA;
                LDSM_X4(ahf[mt][0], ahf[mt][1], ahf[mt][2], ahf[mt][3], aAh + toff);
                LDSM_X4(alf[mt][0], alf[mt][1], alf[mt][2], alf[mt][3], aAl + toff);
            }
            uint32_t bhf[4][2], blf[4][2];
            #pragma unroll
            for (int g = 0; g < 2; g++) {
                const uint32_t toff = (uint32_t)((wn * 32 + g * 16) * ROW_STRIDE) + kb2 + offB;
                LDSM_X4(bhf[2*g][0], bhf[2*g][1], bhf[2*g+1][0], bhf[2*g+1][1], aBh + toff);
                LDSM_X4(blf[2*g][0], blf[2*g][1], blf[2*g+1][0], blf[2*g+1][1], aBl + toff);
            }

            #pragma unroll
            for (int mt = 0; mt < 4; mt++)
                #pragma unroll
                for (int nt = 0; nt < 4; nt++)
                    MMA16816(acc[mt][nt], ahf[mt], bhf[nt][0], bhf[nt][1]);
            #pragma unroll
            for (int mt = 0; mt < 4; mt++)
                #pragma unroll
                for (int nt = 0; nt < 4; nt++)
                    MMA16816(acc[mt][nt], ahf[mt], blf[nt][0], blf[nt][1]);
            #pragma unroll
            for (int mt = 0; mt < 4; mt++)
                #pragma unroll
                for (int nt = 0; nt < 4; nt++)
                    MMA16816(acc[mt][nt], alf[mt], bhf[nt][0], bhf[nt][1]);
        }

        __syncthreads();
        if (t + 2 < KTILES) issue(t & 1, (t + 2) * 32);
    }

    const int g  = lane >> 2;
    const int tq = lane & 3;
    float* Cb = C + (size_t)b * sC;
    const float* Rb = R + (size_t)b * sC;

    #pragma unroll
    for (int mt = 0; mt < 4; mt++) {
        const int row0 = i0 + wm * 64 + mt * 16 + g;
        #pragma unroll
        for (int nt = 0; nt < 4; nt++) {
            const int col = j0 + wn * 32 + nt * 8 + tq * 2;
            float2 v0 = make_float2(acc[mt][nt][0], acc[mt][nt][1]);
            float2 v1 = make_float2(acc[mt][nt][2], acc[mt][nt][3]);
            if (SCALE) { v0.x *= scale; v0.y *= scale; v1.x *= scale; v1.y *= scale; }
            const size_t idx0 = (size_t)row0 * ldc + col;
            const size_t idx1 = (size_t)(row0 + 8) * ldc + col;
            if (RESID) {
                float2 r0 = *(const float2*)&Rb[idx0];
                float2 r1 = *(const float2*)&Rb[idx1];
                v0.x += r0.x; v0.y += r0.y; v1.x += r1.x; v1.y += r1.y;
            }
            *(float2*)&Cb[idx0] = v0;
            *(float2*)&Cb[idx1] = v1;
        }
    }
}

// ---------------------------------------------------------------------------
// softmax: fp32 scores -> bf16 hi/lo probs (unchanged).
// ---------------------------------------------------------------------------
__global__ __launch_bounds__(256) void softmax_kernel()
{
    __shared__ float redmax[8];
    __shared__ float redsum[8];

    const size_t row = blockIdx.x;
    const float* p = g_S + row * NN;
    __nv_bfloat16* ph = g_Ph + row * NN;
    __nv_bfloat16* pl = g_Pl + row * NN;
    const int tid  = threadIdx.x;
    const int lane = tid & 31;
    const int warp = tid >> 5;

    float v[8];
    float mx = -3.4e38f;
    #pragma unroll
    for (int t = 0; t < 8; t++) {
        v[t] = p[tid + t * 256];
        mx = fmaxf(mx, v[t]);
    }
    #pragma unroll
    for (int o = 16; o > 0; o >>= 1)
        mx = fmaxf(mx, __shfl_xor_sync(0xffffffffu, mx, o));
    if (lane == 0) redmax[warp] = mx;
    __syncthreads();
    if (warp == 0) {
        float w = (lane < 8) ? redmax[lane] : -3.4e38f;
        #pragma unroll
        for (int o = 4; o > 0; o >>= 1)
            w = fmaxf(w, __shfl_xor_sync(0xffffffffu, w, o));
        if (lane == 0) redmax[0] = w;
    }
    __syncthreads();
    mx = redmax[0];

    float s = 0.0f;
    #pragma unroll
    for (int t = 0; t < 8; t++) {
        v[t] = __expf(v[t] - mx);
        s += v[t];
    }
    #pragma unroll
    for (int o = 16; o > 0; o >>= 1)
        s += __shfl_xor_sync(0xffffffffu, s, o);
    if (lane == 0) redsum[warp] = s;
    __syncthreads();
    if (warp == 0) {
        float w = (lane < 8) ? redsum[lane] : 0.0f;
        #pragma unroll
        for (int o = 4; o > 0; o >>= 1)
            w += __shfl_xor_sync(0xffffffffu, w, o);
        if (lane == 0) redsum[0] = w;
    }
    __syncthreads();
    const float inv = 1.0f / redsum[0];

    #pragma unroll
    for (int t = 0; t < 8; t++) {
        const float val = v[t] * inv;
        const __nv_bfloat16 h = bsplit_hi(val);
        ph[tid + t * 256] = h;
        pl[tid + t * 256] = bsplit_lo(val, h);
    }
}

// ---------------------------------------------------------------------------
extern "C" void kernel_launch(void* const* d_in, const int* in_sizes, int n_in,
                              void* d_out, int out_size)
{
    const float* x  = (const float*)d_in[0];
    const float* Wq = (const float*)d_in[1];
    const float* bq = (const float*)d_in[2];
    const float* Wk = (const float*)d_in[3];
    const float* bk = (const float*)d_in[4];
    const float* Wv = (const float*)d_in[5];
    const float* bv = (const float*)d_in[6];
    float* out = (float*)d_out;

    void *pQh, *pQl, *pKh, *pKl, *pVh, *pVl, *pS, *pPh, *pPl;
    cudaGetSymbolAddress(&pQh, g_Qh); cudaGetSymbolAddress(&pQl, g_Ql);
    cudaGetSymbolAddress(&pKh, g_Kh); cudaGetSymbolAddress(&pKl, g_Kl);
    cudaGetSymbolAddress(&pVh, g_Vh); cudaGetSymbolAddress(&pVl, g_Vl);
    cudaGetSymbolAddress(&pS,  g_S);
    cudaGetSymbolAddress(&pPh, g_Ph); cudaGetSymbolAddress(&pPl, g_Pl);

    cudaFuncSetAttribute(qkv_mma,
                         cudaFuncAttributeMaxDynamicSharedMemorySize, QSMEM);
    cudaFuncSetAttribute(mma_gemm<CC / 32, true, false>,
                         cudaFuncAttributeMaxDynamicSharedMemorySize, SMEM_TOTAL);
    cudaFuncSetAttribute(mma_gemm<NN / 32, false, true>,
                         cudaFuncAttributeMaxDynamicSharedMemorySize, SMEM_TOTAL);

    dim3 blk(256);
    xsplit_kernel<<<dim3(NN / 32, CC / 32, BB), blk>>>(x);
    wsplit_kernel<<<dim3(CC, 3), blk>>>(Wq, Wk, Wv);
    qkv_mma<<<dim3(NN / 128, CC / 64, BB), blk, QSMEM>>>(bq, bk, bv);

    // scores: C[n][m] = 1/16 * Q[n][:] . K[m][:]   (K=256)
    mma_gemm<CC / 32, true, false><<<dim3(NN / 128, NN / 128, BB), blk, SMEM_TOTAL>>>(
        (const __nv_bfloat16*)pQh, (const __nv_bfloat16*)pQl,
        (const __nv_bfloat16*)pKh, (const __nv_bfloat16*)pKl,
        (float*)pS, nullptr,
        CC, CC, NN, 1.0f / 16.0f,
        (size_t)NN * CC, (size_t)NN * CC, (size_t)NN * NN);

    softmax_kernel<<<BB * NN, 256>>>();

    // out: C[c][n] = V[c][:] . P[n][:]  (K=2048) + x
    mma_gemm<NN / 32, false, true><<<dim3(NN / 128, CC / 128, BB), blk, SMEM_TOTAL>>>(
        (const __nv_bfloat16*)pVh, (const __nv_bfloat16*)pVl,
        (const __nv_bfloat16*)pPh, (const __nv_bfloat16*)pPl,
        out, x,
        NN, NN, NN, 1.0f,
        (size_t)CC * NN, (size_t)NN * NN, (size_t)CC * NN);
}